// round 1
// baseline (speedup 1.0000x reference)
#include <cuda_runtime.h>
#include <math.h>

#define BB   16384
#define EE   8
#define CC   1000
#define DD   59
#define HH1  256
#define HH2  128
#define FEPS 1e-8f
#define LNEPS 1e-5f
#define LN2F 0.69314718055994530942f

// ---------------------------------------------------------------------------
// Kernel A: feature extraction. One block (256 thr) per batch item, persistent.
// ---------------------------------------------------------------------------
__global__ void __launch_bounds__(256) feat_kernel(const float* __restrict__ P,
                                                   float* __restrict__ feats)
{
    __shared__ float sp[EE*CC];     // 32000 B: posteriors for this b, [e][c]
    __shared__ float smean[CC];     // mean over experts
    __shared__ float sL[CC];        // log2(mean + eps)
    __shared__ float s_feat[64];
    __shared__ float s_sq[EE];
    __shared__ float s_red[16];
    __shared__ float s_ge2, s_gent;

    const int tid  = threadIdx.x;
    const int lane = tid & 31;
    const int wid  = tid >> 5;

    for (int b = blockIdx.x; b < BB; b += gridDim.x) {
        // ---- stage posteriors[b] into smem (float4, coalesced) ----
        {
            const float4* src = reinterpret_cast<const float4*>(P + (size_t)b*(EE*CC));
            float4* dst = reinterpret_cast<float4*>(sp);
            for (int i = tid; i < EE*CC/4; i += 256) dst[i] = src[i];
        }
        __syncthreads();

        // ---- phase 1: mean over experts, log2(mean+eps), global sums ----
        float ge2 = 0.f, gent = 0.f;   // sum mean^2, sum mean*log2(mean+eps)
        for (int c = tid; c < CC; c += 256) {
            float s = 0.f;
            #pragma unroll
            for (int e = 0; e < EE; e++) s += sp[e*CC + c];
            float m = s * 0.125f;
            float L = __log2f(m + FEPS);
            smean[c] = m;
            sL[c]    = L;
            ge2  += m * m;
            gent += m * L;
        }
        #pragma unroll
        for (int off = 16; off; off >>= 1) {
            ge2  += __shfl_xor_sync(0xffffffffu, ge2,  off);
            gent += __shfl_xor_sync(0xffffffffu, gent, off);
        }
        if (lane == 0) { s_red[wid] = ge2; s_red[8 + wid] = gent; }
        __syncthreads();
        if (tid == 0) {
            float a = 0.f, g = 0.f;
            #pragma unroll
            for (int w = 0; w < 8; w++) { a += s_red[w]; g += s_red[8 + w]; }
            s_ge2 = a; s_gent = g;
        }
        __syncthreads();

        // ---- phase 2: one warp per expert, single fused scan ----
        {
            const float mn = fmaxf(sqrtf(s_ge2), FEPS);   // ||mean_p||
            const float4* row = reinterpret_cast<const float4*>(sp + wid*CC);
            const float4* m4  = reinterpret_cast<const float4*>(smean);
            const float4* L4  = reinterpret_cast<const float4*>(sL);

            float slp = 0.f;   // sum p*log2(p+eps)
            float sq  = 0.f;   // sum p^2
            float dtv = 0.f;   // sum p*mean
            float pl  = 0.f;   // sum p*log2(mean+eps)
            float v0 = -1.f, v1 = -1.f, v2 = -1.f, v3 = -1.f, v4 = -1.f;

            #pragma unroll
            for (int k = 0; k < 8; k++) {
                int t = lane + 32*k;
                if (t < CC/4) {
                    float4 p  = row[t];
                    float4 mm = m4[t];
                    float4 LL = L4[t];
                    #define DOELEM(px, mx, lx)                                   \
                    {                                                            \
                        float lp = __log2f((px) + FEPS);                         \
                        slp += (px)*lp;                                          \
                        sq  += (px)*(px);                                        \
                        dtv += (px)*(mx);                                        \
                        pl  += (px)*(lx);                                        \
                        if ((px) > v4) {                                         \
                            v4 = (px);                                           \
                            if (v4 > v3) { float tt=v3; v3=v4; v4=tt; }          \
                            if (v3 > v2) { float tt=v2; v2=v3; v3=tt; }          \
                            if (v2 > v1) { float tt=v1; v1=v2; v2=tt; }          \
                            if (v1 > v0) { float tt=v0; v0=v1; v1=tt; }          \
                        }                                                        \
                    }
                    DOELEM(p.x, mm.x, LL.x)
                    DOELEM(p.y, mm.y, LL.y)
                    DOELEM(p.z, mm.z, LL.z)
                    DOELEM(p.w, mm.w, LL.w)
                    #undef DOELEM
                }
            }
            // warp-reduce the 4 sums
            #pragma unroll
            for (int off = 16; off; off >>= 1) {
                slp += __shfl_xor_sync(0xffffffffu, slp, off);
                sq  += __shfl_xor_sync(0xffffffffu, sq,  off);
                dtv += __shfl_xor_sync(0xffffffffu, dtv, off);
                pl  += __shfl_xor_sync(0xffffffffu, pl,  off);
            }
            // merge lane-local sorted top-5 lists -> global top-5 (5 rounds)
            float o0, o1, o2, o3, o4;
            #pragma unroll
            for (int r = 0; r < 5; r++) {
                float cur = v0;
                float mx = cur;
                #pragma unroll
                for (int off = 16; off; off >>= 1)
                    mx = fmaxf(mx, __shfl_xor_sync(0xffffffffu, mx, off));
                unsigned msk = __ballot_sync(0xffffffffu, cur == mx);
                int src = __ffs(msk) - 1;
                if (lane == src) { v0 = v1; v1 = v2; v2 = v3; v3 = v4; v4 = -1.f; }
                if (r == 0) o0 = mx; else if (r == 1) o1 = mx;
                else if (r == 2) o2 = mx; else if (r == 3) o3 = mx; else o4 = mx;
            }

            if (lane == 0) {
                float ent  = -slp * LN2F;
                float mass = o0 + o1 + o2 + o3 + o4;
                float pn   = fmaxf(sqrtf(sq), FEPS);
                s_feat[0*EE + wid] = ent;                    // entropy
                s_feat[1*EE + wid] = mass;                   // topk_mass
                s_feat[2*EE + wid] = 1.f - mass;             // residual
                s_feat[3*EE + wid] = o0;                     // max_probs
                s_feat[4*EE + wid] = o0 - o1;                // top_gap
                s_feat[5*EE + wid] = dtv / (pn * mn);        // cos
                s_feat[6*EE + wid] = (slp - pl) * LN2F;      // kl
                s_sq[wid] = sq;
            }
        }
        __syncthreads();

        if (tid == 0) {
            float totsq = 0.f;
            #pragma unroll
            for (int e = 0; e < EE; e++) totsq += s_sq[e];
            float mcv = (totsq - 8.f * s_ge2) * (1.f / 7000.f);  // mean class var (ddof=1)
            float mu = 0.f;
            #pragma unroll
            for (int e = 0; e < EE; e++) mu += s_feat[3*EE + e];
            mu *= 0.125f;
            float var = 0.f;
            #pragma unroll
            for (int e = 0; e < EE; e++) {
                float d = s_feat[3*EE + e] - mu;
                var += d * d;
            }
            s_feat[56] = -s_gent * LN2F;         // mean_ent
            s_feat[57] = mcv;                    // mean_class_var
            s_feat[58] = sqrtf(var * (1.f/7.f)); // std_max (ddof=1)
        }
        __syncthreads();

        if (tid < DD) {
            float v = s_feat[tid];
            v = fminf(fmaxf(v, -100.f), 100.f);
            feats[(size_t)b * DD + tid] = v;
        }
        __syncthreads();   // protect smem before next iteration
    }
}

// ---------------------------------------------------------------------------
// Kernel B: MLP (59 -> LN/relu 256 -> LN/relu 128 -> 8 -> softmax).
// Persistent blocks, all weights staged in dynamic smem, 4 rows per iteration.
// ---------------------------------------------------------------------------
#define MROWS 4

__global__ void __launch_bounds__(256) mlp_kernel(
    const float* __restrict__ feats,
    const float* __restrict__ W1, const float* __restrict__ b1,
    const float* __restrict__ g1, const float* __restrict__ be1,
    const float* __restrict__ W2, const float* __restrict__ b2,
    const float* __restrict__ g2, const float* __restrict__ be2,
    const float* __restrict__ W3, const float* __restrict__ b3,
    float* __restrict__ wout, float* __restrict__ lout)
{
    extern __shared__ float sm[];
    float* sW1  = sm;                      // 59*256
    float* sW2  = sW1  + DD*HH1;           // 256*128
    float* sW3  = sW2  + HH1*HH2;          // 128*8
    float* sb1  = sW3  + HH2*EE;           // 256
    float* sg1  = sb1  + HH1;
    float* sbe1 = sg1  + HH1;
    float* sb2  = sbe1 + HH1;              // 128
    float* sg2  = sb2  + HH2;
    float* sbe2 = sg2  + HH2;
    float* sb3  = sbe2 + HH2;              // 8
    float* sf   = sb3  + EE;               // 4*59
    float* sh1  = sf   + MROWS*DD;         // 4*256
    float* sh2  = sh1  + MROWS*HH1;        // 4*128
    float* spart= sh2  + MROWS*HH2;        // 2*128*4
    float* slog = spart+ 2*HH2*MROWS;      // 4*8
    float* sred = slog + MROWS*EE;         // 64
    float* smu  = sred + 64;               // 4
    float* srs  = smu  + 4;                // 4

    const int tid  = threadIdx.x;
    const int lane = tid & 31;
    const int wid  = tid >> 5;

    // stage weights once
    for (int i = tid; i < DD*HH1;  i += 256) sW1[i] = W1[i];
    for (int i = tid; i < HH1*HH2; i += 256) sW2[i] = W2[i];
    for (int i = tid; i < HH2*EE;  i += 256) sW3[i] = W3[i];
    for (int i = tid; i < HH1;     i += 256) { sb1[i] = b1[i]; sg1[i] = g1[i]; sbe1[i] = be1[i]; }
    for (int i = tid; i < HH2;     i += 256) { sb2[i] = b2[i]; sg2[i] = g2[i]; sbe2[i] = be2[i]; }
    if (tid < EE) sb3[tid] = b3[tid];
    __syncthreads();

    const int nchunks = BB / MROWS;   // 4096
    for (int chunk = blockIdx.x; chunk < nchunks; chunk += gridDim.x) {
        const int row0 = chunk * MROWS;

        for (int i = tid; i < MROWS*DD; i += 256)
            sf[i] = feats[(size_t)row0 * DD + i];
        __syncthreads();

        // ---- layer 1: 59 -> 256 ----
        float acc[MROWS];
        {
            const int j = tid;
            #pragma unroll
            for (int r = 0; r < MROWS; r++) acc[r] = sb1[j];
            for (int i = 0; i < DD; i++) {
                float w = sW1[i*HH1 + j];
                #pragma unroll
                for (int r = 0; r < MROWS; r++) acc[r] += sf[r*DD + i] * w;
            }
        }
        // LN over 256 (block-wide per row)
        {
            float sv[MROWS], sq2[MROWS];
            #pragma unroll
            for (int r = 0; r < MROWS; r++) { sv[r] = acc[r]; sq2[r] = acc[r]*acc[r]; }
            #pragma unroll
            for (int off = 16; off; off >>= 1) {
                #pragma unroll
                for (int r = 0; r < MROWS; r++) {
                    sv[r]  += __shfl_xor_sync(0xffffffffu, sv[r],  off);
                    sq2[r] += __shfl_xor_sync(0xffffffffu, sq2[r], off);
                }
            }
            if (lane == 0) {
                #pragma unroll
                for (int r = 0; r < MROWS; r++) {
                    sred[wid*4 + r]      = sv[r];
                    sred[32 + wid*4 + r] = sq2[r];
                }
            }
        }
        __syncthreads();
        if (tid < MROWS) {
            float a = 0.f, q = 0.f;
            #pragma unroll
            for (int w = 0; w < 8; w++) { a += sred[w*4 + tid]; q += sred[32 + w*4 + tid]; }
            float mu  = a * (1.f/256.f);
            float var = q * (1.f/256.f) - mu*mu;
            smu[tid] = mu;
            srs[tid] = rsqrtf(var + LNEPS);
        }
        __syncthreads();
        {
            const int j = tid;
            #pragma unroll
            for (int r = 0; r < MROWS; r++) {
                float h = (acc[r] - smu[r]) * srs[r] * sg1[j] + sbe1[j];
                sh1[r*HH1 + j] = fmaxf(h, 0.f);
            }
        }
        __syncthreads();

        // ---- layer 2: 256 -> 128 (split-K over 2 halves) ----
        {
            const int j    = tid & (HH2 - 1);
            const int half = tid >> 7;
            float a2[MROWS];
            #pragma unroll
            for (int r = 0; r < MROWS; r++) a2[r] = 0.f;
            const int i0 = half * 128;
            for (int i = i0; i < i0 + 128; i++) {
                float w = sW2[i*HH2 + j];
                #pragma unroll
                for (int r = 0; r < MROWS; r++) a2[r] += sh1[r*HH1 + i] * w;
            }
            #pragma unroll
            for (int r = 0; r < MROWS; r++) spart[(half*HH2 + j)*4 + r] = a2[r];
        }
        __syncthreads();
        float acc3[MROWS];
        if (tid < HH2) {
            #pragma unroll
            for (int r = 0; r < MROWS; r++)
                acc3[r] = spart[tid*4 + r] + spart[(HH2 + tid)*4 + r] + sb2[tid];
            float sv[MROWS], sq2[MROWS];
            #pragma unroll
            for (int r = 0; r < MROWS; r++) { sv[r] = acc3[r]; sq2[r] = acc3[r]*acc3[r]; }
            #pragma unroll
            for (int off = 16; off; off >>= 1) {
                #pragma unroll
                for (int r = 0; r < MROWS; r++) {
                    sv[r]  += __shfl_xor_sync(0xffffffffu, sv[r],  off);
                    sq2[r] += __shfl_xor_sync(0xffffffffu, sq2[r], off);
                }
            }
            if (lane == 0) {
                #pragma unroll
                for (int r = 0; r < MROWS; r++) {
                    sred[wid*4 + r]      = sv[r];
                    sred[32 + wid*4 + r] = sq2[r];
                }
            }
        }
        __syncthreads();
        if (tid < MROWS) {
            float a = 0.f, q = 0.f;
            #pragma unroll
            for (int w = 0; w < 4; w++) { a += sred[w*4 + tid]; q += sred[32 + w*4 + tid]; }
            float mu  = a * (1.f/128.f);
            float var = q * (1.f/128.f) - mu*mu;
            smu[tid] = mu;
            srs[tid] = rsqrtf(var + LNEPS);
        }
        __syncthreads();
        if (tid < HH2) {
            #pragma unroll
            for (int r = 0; r < MROWS; r++) {
                float h = (acc3[r] - smu[r]) * srs[r] * sg2[tid] + sbe2[tid];
                sh2[r*HH2 + tid] = fmaxf(h, 0.f);
            }
        }
        __syncthreads();

        // ---- layer 3 + softmax ----
        if (tid < MROWS*EE) {
            const int r = tid >> 3;
            const int o = tid & 7;
            float a = sb3[o];
            for (int i = 0; i < HH2; i++) a += sh2[r*HH2 + i] * sW3[i*EE + o];
            slog[r*EE + o] = a;
        }
        __syncthreads();
        if (tid < MROWS*EE) {
            const int r = tid >> 3;
            const int o = tid & 7;
            float lg = slog[r*EE + o];
            float mx = lg;
            #pragma unroll
            for (int off = 4; off; off >>= 1)
                mx = fmaxf(mx, __shfl_xor_sync(0xffffffffu, mx, off));
            float ex = __expf(lg - mx);
            float sme = ex;
            #pragma unroll
            for (int off = 4; off; off >>= 1)
                sme += __shfl_xor_sync(0xffffffffu, sme, off);
            const int row = row0 + r;
            lout[(size_t)row*EE + o] = lg;
            wout[(size_t)row*EE + o] = ex / sme;
        }
        __syncthreads();
    }
}

// ---------------------------------------------------------------------------
extern "C" void kernel_launch(void* const* d_in, const int* in_sizes, int n_in,
                              void* d_out, int out_size)
{
    (void)in_sizes; (void)n_in; (void)out_size;
    const float* P   = (const float*)d_in[0];
    const float* W1  = (const float*)d_in[1];
    const float* b1  = (const float*)d_in[2];
    const float* g1  = (const float*)d_in[3];
    const float* be1 = (const float*)d_in[4];
    const float* W2  = (const float*)d_in[5];
    const float* b2  = (const float*)d_in[6];
    const float* g2  = (const float*)d_in[7];
    const float* be2 = (const float*)d_in[8];
    const float* W3  = (const float*)d_in[9];
    const float* b3  = (const float*)d_in[10];

    float* out   = (float*)d_out;
    float* wout  = out;                    // weights: B*8
    float* lout  = out + (size_t)BB*EE;    // logits:  B*8
    float* feats = out + (size_t)2*BB*EE;  // feats:   B*59

    feat_kernel<<<740, 256>>>(P, feats);

    const size_t smemB = (size_t)(DD*HH1 + HH1*HH2 + HH2*EE
                                  + 3*HH1 + 3*HH2 + EE
                                  + MROWS*DD + MROWS*HH1 + MROWS*HH2
                                  + 2*HH2*MROWS + MROWS*EE + 64 + 8) * sizeof(float);
    cudaFuncSetAttribute(mlp_kernel, cudaFuncAttributeMaxDynamicSharedMemorySize, (int)smemB);
    mlp_kernel<<<148, 256, smemB>>>(feats, W1, b1, g1, be1, W2, b2, g2, be2, W3, b3,
                                    wout, lout);
}

// round 2
// speedup vs baseline: 1.1361x; 1.1361x over previous
#include <cuda_runtime.h>
#include <math.h>

#define BB   16384
#define EE   8
#define CC   1000
#define DD   59
#define HH1  256
#define HH2  128
#define FEPS 1e-8f
#define LNEPS 1e-5f
#define LN2F 0.69314718055994530942f

// ---------------------------------------------------------------------------
__device__ __forceinline__ void cp_async16(void* smem_ptr, const void* gmem) {
    unsigned s = (unsigned)__cvta_generic_to_shared(smem_ptr);
    asm volatile("cp.async.cg.shared.global [%0], [%1], 16;\n" :: "r"(s), "l"(gmem));
}
#define CP_COMMIT() asm volatile("cp.async.commit_group;\n" ::: "memory")
#define CP_WAIT1()  asm volatile("cp.async.wait_group 1;\n" ::: "memory")

// ---------------------------------------------------------------------------
// Kernel A: feature extraction. 256 thr/block, cp.async double-buffered.
// dynamic smem: buf[2][8000] + smean[1000] + sL[1000]  = 72000 B
// ---------------------------------------------------------------------------
__global__ void __launch_bounds__(256) feat_kernel(const float* __restrict__ P,
                                                   float* __restrict__ feats)
{
    extern __shared__ float dyn[];
    float* buf0  = dyn;               // 8000
    float* buf1  = dyn + 8000;        // 8000
    float* smean = dyn + 16000;       // 1000
    float* sL    = dyn + 17000;       // 1000

    __shared__ float s_feat[64];
    __shared__ float s_sq[EE];
    __shared__ float s_red[16];
    __shared__ float s_ge2, s_gent;

    const int tid  = threadIdx.x;
    const int lane = tid & 31;
    const int wid  = tid >> 5;

    float* bufs[2] = {buf0, buf1};

    // prime the pipeline
    int b0 = blockIdx.x;
    if (b0 < BB) {
        const float4* src = reinterpret_cast<const float4*>(P + (size_t)b0*(EE*CC));
        float4* dst = reinterpret_cast<float4*>(buf0);
        for (int i = tid; i < EE*CC/4; i += 256) cp_async16(&dst[i], &src[i]);
    }
    CP_COMMIT();

    int cur = 0;
    for (int b = b0; b < BB; b += gridDim.x) {
        int nb = b + gridDim.x;
        if (nb < BB) {
            const float4* src = reinterpret_cast<const float4*>(P + (size_t)nb*(EE*CC));
            float4* dst = reinterpret_cast<float4*>(bufs[cur^1]);
            for (int i = tid; i < EE*CC/4; i += 256) cp_async16(&dst[i], &src[i]);
        }
        CP_COMMIT();
        CP_WAIT1();            // current buffer ready
        __syncthreads();

        const float* sp = bufs[cur];

        // ---- phase 1: mean over experts (float4), log2(mean+eps), global sums ----
        float ge2 = 0.f, gent = 0.f;
        if (tid < CC/4) {
            const float4* pb = reinterpret_cast<const float4*>(sp);
            float4 m = make_float4(0.f, 0.f, 0.f, 0.f);
            #pragma unroll
            for (int e = 0; e < EE; e++) {
                float4 p = pb[e*(CC/4) + tid];
                m.x += p.x; m.y += p.y; m.z += p.z; m.w += p.w;
            }
            m.x *= 0.125f; m.y *= 0.125f; m.z *= 0.125f; m.w *= 0.125f;
            float4 L;
            L.x = __log2f(m.x + FEPS);
            L.y = __log2f(m.y + FEPS);
            L.z = __log2f(m.z + FEPS);
            L.w = __log2f(m.w + FEPS);
            reinterpret_cast<float4*>(smean)[tid] = m;
            reinterpret_cast<float4*>(sL)[tid]    = L;
            ge2  = m.x*m.x + m.y*m.y + m.z*m.z + m.w*m.w;
            gent = m.x*L.x + m.y*L.y + m.z*L.z + m.w*L.w;
        }
        #pragma unroll
        for (int off = 16; off; off >>= 1) {
            ge2  += __shfl_xor_sync(0xffffffffu, ge2,  off);
            gent += __shfl_xor_sync(0xffffffffu, gent, off);
        }
        if (lane == 0) { s_red[wid] = ge2; s_red[8 + wid] = gent; }
        __syncthreads();
        if (tid == 0) {
            float a = 0.f, g = 0.f;
            #pragma unroll
            for (int w = 0; w < 8; w++) { a += s_red[w]; g += s_red[8 + w]; }
            s_ge2 = a; s_gent = g;
        }
        __syncthreads();

        // ---- phase 2: one warp per expert, fused scan ----
        {
            const float mn = fmaxf(sqrtf(s_ge2), FEPS);
            const float4* row = reinterpret_cast<const float4*>(sp + wid*CC);
            const float4* m4  = reinterpret_cast<const float4*>(smean);
            const float4* L4  = reinterpret_cast<const float4*>(sL);

            float slp = 0.f, sq = 0.f, dtv = 0.f, pl = 0.f;
            float v0 = -1.f, v1 = -1.f, v2 = -1.f, v3 = -1.f, v4 = -1.f;

            #pragma unroll
            for (int k = 0; k < 8; k++) {
                int t = lane + 32*k;
                if (t < CC/4) {
                    float4 p  = row[t];
                    float4 mm = m4[t];
                    float4 LL = L4[t];
                    #define DOELEM(px, mx, lx)                                   \
                    {                                                            \
                        float lp = __log2f((px) + FEPS);                         \
                        slp += (px)*lp;                                          \
                        sq  += (px)*(px);                                        \
                        dtv += (px)*(mx);                                        \
                        pl  += (px)*(lx);                                        \
                        if ((px) > v4) {                                         \
                            v4 = (px);                                           \
                            if (v4 > v3) { float tt=v3; v3=v4; v4=tt; }          \
                            if (v3 > v2) { float tt=v2; v2=v3; v3=tt; }          \
                            if (v2 > v1) { float tt=v1; v1=v2; v2=tt; }          \
                            if (v1 > v0) { float tt=v0; v0=v1; v1=tt; }          \
                        }                                                        \
                    }
                    DOELEM(p.x, mm.x, LL.x)
                    DOELEM(p.y, mm.y, LL.y)
                    DOELEM(p.z, mm.z, LL.z)
                    DOELEM(p.w, mm.w, LL.w)
                    #undef DOELEM
                }
            }
            #pragma unroll
            for (int off = 16; off; off >>= 1) {
                slp += __shfl_xor_sync(0xffffffffu, slp, off);
                sq  += __shfl_xor_sync(0xffffffffu, sq,  off);
                dtv += __shfl_xor_sync(0xffffffffu, dtv, off);
                pl  += __shfl_xor_sync(0xffffffffu, pl,  off);
            }
            float o0, o1, o2, o3, o4;
            #pragma unroll
            for (int r = 0; r < 5; r++) {
                float cur_v = v0;
                float mx = cur_v;
                #pragma unroll
                for (int off = 16; off; off >>= 1)
                    mx = fmaxf(mx, __shfl_xor_sync(0xffffffffu, mx, off));
                unsigned msk = __ballot_sync(0xffffffffu, cur_v == mx);
                int src = __ffs(msk) - 1;
                if (lane == src) { v0 = v1; v1 = v2; v2 = v3; v3 = v4; v4 = -1.f; }
                if (r == 0) o0 = mx; else if (r == 1) o1 = mx;
                else if (r == 2) o2 = mx; else if (r == 3) o3 = mx; else o4 = mx;
            }

            if (lane == 0) {
                float ent  = -slp * LN2F;
                float mass = o0 + o1 + o2 + o3 + o4;
                float pn   = fmaxf(sqrtf(sq), FEPS);
                s_feat[0*EE + wid] = ent;
                s_feat[1*EE + wid] = mass;
                s_feat[2*EE + wid] = 1.f - mass;
                s_feat[3*EE + wid] = o0;
                s_feat[4*EE + wid] = o0 - o1;
                s_feat[5*EE + wid] = dtv / (pn * mn);
                s_feat[6*EE + wid] = (slp - pl) * LN2F;
                s_sq[wid] = sq;
            }
        }
        __syncthreads();

        if (tid == 0) {
            float totsq = 0.f;
            #pragma unroll
            for (int e = 0; e < EE; e++) totsq += s_sq[e];
            float mcv = (totsq - 8.f * s_ge2) * (1.f / 7000.f);
            float mu = 0.f;
            #pragma unroll
            for (int e = 0; e < EE; e++) mu += s_feat[3*EE + e];
            mu *= 0.125f;
            float var = 0.f;
            #pragma unroll
            for (int e = 0; e < EE; e++) {
                float d = s_feat[3*EE + e] - mu;
                var += d * d;
            }
            s_feat[56] = -s_gent * LN2F;
            s_feat[57] = mcv;
            s_feat[58] = sqrtf(var * (1.f/7.f));
        }
        __syncthreads();

        if (tid < DD) {
            float v = s_feat[tid];
            v = fminf(fmaxf(v, -100.f), 100.f);
            feats[(size_t)b * DD + tid] = v;
        }
        __syncthreads();   // all reads of bufs[cur] done before it is refilled
        cur ^= 1;
    }
}

// ---------------------------------------------------------------------------
// Kernel B: MLP. 512 threads, 2 groups x 4 rows = 8 rows per iteration.
// W1/W3/biases in smem (~92KB -> 2 blocks/SM, 32 warps). W2 read from L2.
// ---------------------------------------------------------------------------
#define MROWS  4
#define GROUPS 2

__global__ void __launch_bounds__(512) mlp_kernel(
    const float* __restrict__ feats,
    const float* __restrict__ W1, const float* __restrict__ b1,
    const float* __restrict__ g1, const float* __restrict__ be1,
    const float* __restrict__ W2, const float* __restrict__ b2,
    const float* __restrict__ g2, const float* __restrict__ be2,
    const float* __restrict__ W3, const float* __restrict__ b3,
    float* __restrict__ wout, float* __restrict__ lout)
{
    extern __shared__ float sm[];
    float* sW1  = sm;                        // 59*256 = 15104
    float* sW3  = sW1  + DD*HH1;             // 128*8  = 1024
    float* sb1  = sW3  + HH2*EE;             // 256
    float* sg1  = sb1  + HH1;
    float* sbe1 = sg1  + HH1;
    float* sb2  = sbe1 + HH1;                // 128
    float* sg2  = sb2  + HH2;
    float* sbe2 = sg2  + HH2;
    float* sb3  = sbe2 + HH2;                // 8
    float* sf   = sb3  + EE;                 // 8*59   = 472
    float* sh1  = sf   + GROUPS*MROWS*DD;    // 8*256  = 2048
    float* sh2  = sh1  + GROUPS*MROWS*HH1;   // 8*128  = 1024
    float* spart= sh2  + GROUPS*MROWS*HH2;   // 2*1024 = 2048
    float* slog = spart+ GROUPS*2*HH2*MROWS; // 64
    float* sred = slog + GROUPS*MROWS*EE;    // 128 (sums at 0, squares at 64)
    float* smu  = sred + 128;                // 8
    float* srs  = smu  + GROUPS*MROWS;       // 8

    const int tid  = threadIdx.x;
    const int lane = tid & 31;
    const int wid  = tid >> 5;               // 0..15
    const int g    = tid >> 8;               // 0..1
    const int gtid = tid & 255;

    for (int i = tid; i < DD*HH1;  i += 512) sW1[i] = W1[i];
    for (int i = tid; i < HH2*EE;  i += 512) sW3[i] = W3[i];
    for (int i = tid; i < HH1;     i += 512) { sb1[i] = b1[i]; sg1[i] = g1[i]; sbe1[i] = be1[i]; }
    for (int i = tid; i < HH2;     i += 512) { sb2[i] = b2[i]; sg2[i] = g2[i]; sbe2[i] = be2[i]; }
    if (tid < EE) sb3[tid] = b3[tid];
    __syncthreads();

    const int RPC = GROUPS * MROWS;          // 8 rows per chunk
    const int nchunks = BB / RPC;            // 2048
    for (int chunk = blockIdx.x; chunk < nchunks; chunk += gridDim.x) {
        const int row0 = chunk * RPC;

        for (int i = tid; i < RPC*DD; i += 512)
            sf[i] = feats[(size_t)row0 * DD + i];
        __syncthreads();

        // ---- layer 1: 59 -> 256 ----
        float acc[MROWS];
        {
            const int j = gtid;
            #pragma unroll
            for (int r = 0; r < MROWS; r++) acc[r] = sb1[j];
            for (int i = 0; i < DD; i++) {
                float w = sW1[i*HH1 + j];
                #pragma unroll
                for (int r = 0; r < MROWS; r++) acc[r] += sf[(g*MROWS + r)*DD + i] * w;
            }
        }
        {
            float sv[MROWS], sq2[MROWS];
            #pragma unroll
            for (int r = 0; r < MROWS; r++) { sv[r] = acc[r]; sq2[r] = acc[r]*acc[r]; }
            #pragma unroll
            for (int off = 16; off; off >>= 1) {
                #pragma unroll
                for (int r = 0; r < MROWS; r++) {
                    sv[r]  += __shfl_xor_sync(0xffffffffu, sv[r],  off);
                    sq2[r] += __shfl_xor_sync(0xffffffffu, sq2[r], off);
                }
            }
            if (lane == 0) {
                #pragma unroll
                for (int r = 0; r < MROWS; r++) {
                    sred[wid*4 + r]      = sv[r];
                    sred[64 + wid*4 + r] = sq2[r];
                }
            }
        }
        __syncthreads();
        if (tid < RPC) {
            const int gg = tid >> 2, r = tid & 3; (void)r;
            float a = 0.f, q = 0.f;
            #pragma unroll
            for (int w = 0; w < 8; w++) {
                a += sred[(gg*8 + w)*4 + (tid & 3)];
                q += sred[64 + (gg*8 + w)*4 + (tid & 3)];
            }
            float mu  = a * (1.f/256.f);
            float var = q * (1.f/256.f) - mu*mu;
            smu[tid] = mu;
            srs[tid] = rsqrtf(var + LNEPS);
        }
        __syncthreads();
        {
            const int j = gtid;
            #pragma unroll
            for (int r = 0; r < MROWS; r++) {
                float h = (acc[r] - smu[g*MROWS + r]) * srs[g*MROWS + r] * sg1[j] + sbe1[j];
                sh1[(g*MROWS + r)*HH1 + j] = fmaxf(h, 0.f);
            }
        }
        __syncthreads();

        // ---- layer 2: 256 -> 128, W2 from global (L2-resident), split-K=2 ----
        {
            const int j    = gtid & (HH2 - 1);
            const int half = gtid >> 7;
            float a2[MROWS];
            #pragma unroll
            for (int r = 0; r < MROWS; r++) a2[r] = 0.f;
            const int i0 = half * 128;
            #pragma unroll 4
            for (int i = i0; i < i0 + 128; i++) {
                float w = __ldg(&W2[i*HH2 + j]);
                #pragma unroll
                for (int r = 0; r < MROWS; r++) a2[r] += sh1[(g*MROWS + r)*HH1 + i] * w;
            }
            #pragma unroll
            for (int r = 0; r < MROWS; r++)
                spart[g*(2*HH2*MROWS) + (half*HH2 + j)*MROWS + r] = a2[r];
        }
        __syncthreads();
        float acc3[MROWS];
        if (gtid < HH2) {
            const int j = gtid;
            #pragma unroll
            for (int r = 0; r < MROWS; r++)
                acc3[r] = spart[g*(2*HH2*MROWS) + j*MROWS + r]
                        + spart[g*(2*HH2*MROWS) + (HH2 + j)*MROWS + r] + sb2[j];
            float sv[MROWS], sq2[MROWS];
            #pragma unroll
            for (int r = 0; r < MROWS; r++) { sv[r] = acc3[r]; sq2[r] = acc3[r]*acc3[r]; }
            #pragma unroll
            for (int off = 16; off; off >>= 1) {
                #pragma unroll
                for (int r = 0; r < MROWS; r++) {
                    sv[r]  += __shfl_xor_sync(0xffffffffu, sv[r],  off);
                    sq2[r] += __shfl_xor_sync(0xffffffffu, sq2[r], off);
                }
            }
            if (lane == 0) {
                #pragma unroll
                for (int r = 0; r < MROWS; r++) {
                    sred[wid*4 + r]      = sv[r];
                    sred[64 + wid*4 + r] = sq2[r];
                }
            }
        }
        __syncthreads();
        if (tid < RPC) {
            const int gg = tid >> 2;
            float a = 0.f, q = 0.f;
            #pragma unroll
            for (int w = 0; w < 4; w++) {
                a += sred[(gg*8 + w)*4 + (tid & 3)];
                q += sred[64 + (gg*8 + w)*4 + (tid & 3)];
            }
            float mu  = a * (1.f/128.f);
            float var = q * (1.f/128.f) - mu*mu;
            smu[tid] = mu;
            srs[tid] = rsqrtf(var + LNEPS);
        }
        __syncthreads();
        if (gtid < HH2) {
            #pragma unroll
            for (int r = 0; r < MROWS; r++) {
                float h = (acc3[r] - smu[g*MROWS + r]) * srs[g*MROWS + r] * sg2[gtid] + sbe2[gtid];
                sh2[(g*MROWS + r)*HH2 + gtid] = fmaxf(h, 0.f);
            }
        }
        __syncthreads();

        // ---- layer 3 + softmax ----
        if (tid < RPC*EE) {
            const int r = tid >> 3;      // 0..7 (global row within chunk)
            const int o = tid & 7;
            float a = sb3[o];
            #pragma unroll 8
            for (int i = 0; i < HH2; i++) a += sh2[r*HH2 + i] * sW3[i*EE + o];
            slog[r*EE + o] = a;

            float mx = a;
            #pragma unroll
            for (int off = 4; off; off >>= 1)
                mx = fmaxf(mx, __shfl_xor_sync(0xffffffffu, mx, off));
            float ex = __expf(a - mx);
            float sme = ex;
            #pragma unroll
            for (int off = 4; off; off >>= 1)
                sme += __shfl_xor_sync(0xffffffffu, sme, off);
            const int row = row0 + r;
            lout[(size_t)row*EE + o] = a;
            wout[(size_t)row*EE + o] = ex / sme;
        }
        __syncthreads();
    }
}

// ---------------------------------------------------------------------------
extern "C" void kernel_launch(void* const* d_in, const int* in_sizes, int n_in,
                              void* d_out, int out_size)
{
    (void)in_sizes; (void)n_in; (void)out_size;
    const float* P   = (const float*)d_in[0];
    const float* W1  = (const float*)d_in[1];
    const float* b1  = (const float*)d_in[2];
    const float* g1  = (const float*)d_in[3];
    const float* be1 = (const float*)d_in[4];
    const float* W2  = (const float*)d_in[5];
    const float* b2  = (const float*)d_in[6];
    const float* g2  = (const float*)d_in[7];
    const float* be2 = (const float*)d_in[8];
    const float* W3  = (const float*)d_in[9];
    const float* b3  = (const float*)d_in[10];

    float* out   = (float*)d_out;
    float* wout  = out;                    // weights: B*8
    float* lout  = out + (size_t)BB*EE;    // logits:  B*8
    float* feats = out + (size_t)2*BB*EE;  // feats:   B*59

    const size_t smemA = (size_t)(2*EE*CC + 2*CC) * sizeof(float);  // 72000 B
    cudaFuncSetAttribute(feat_kernel, cudaFuncAttributeMaxDynamicSharedMemorySize, (int)smemA);
    feat_kernel<<<444, 256, smemA>>>(P, feats);

    const size_t smemB = (size_t)(DD*HH1 + HH2*EE
                                  + 3*HH1 + 3*HH2 + EE
                                  + GROUPS*MROWS*DD + GROUPS*MROWS*HH1 + GROUPS*MROWS*HH2
                                  + GROUPS*2*HH2*MROWS + GROUPS*MROWS*EE + 128 + 16)
                         * sizeof(float);
    cudaFuncSetAttribute(mlp_kernel, cudaFuncAttributeMaxDynamicSharedMemorySize, (int)smemB);
    mlp_kernel<<<296, 512, smemB>>>(feats, W1, b1, g1, be1, W2, b2, g2, be2, W3, b3,
                                    wout, lout);
}